// round 5
// baseline (speedup 1.0000x reference)
#include <cuda_runtime.h>
#include <cstdint>
#include <math.h>

// Pacemaker: OU process + Bernoulli spikes, bit-matching JAX threefry2x32
// (partitionable/fold-like semantics) + XLA erfinv.
//
// T=16384 steps, N=8192 neurons, out = f32 spikes [T, N].

#define T_STEPS 16384
#define N_NEUR  8192

// per-step derived keys: (kn0, kn1, kb0, kb1)
__device__ uint4 g_keys[T_STEPS];
// noise scratch, NEURON-major: g_noise[i * T_STEPS + t]
__device__ __align__(16) float g_noise[(size_t)T_STEPS * N_NEUR];

// ---------------------------------------------------------------------------
// threefry2x32 (20 rounds) — identical to jax._src.prng.threefry2x32
// ---------------------------------------------------------------------------
__device__ __forceinline__ void tf_round4(uint32_t& x0, uint32_t& x1,
                                          int r0, int r1, int r2, int r3) {
  x0 += x1; x1 = __funnelshift_l(x1, x1, r0); x1 ^= x0;
  x0 += x1; x1 = __funnelshift_l(x1, x1, r1); x1 ^= x0;
  x0 += x1; x1 = __funnelshift_l(x1, x1, r2); x1 ^= x0;
  x0 += x1; x1 = __funnelshift_l(x1, x1, r3); x1 ^= x0;
}

__device__ __forceinline__ uint2 threefry2x32(uint32_t k0, uint32_t k1,
                                              uint32_t x0, uint32_t x1) {
  uint32_t ks2 = k0 ^ k1 ^ 0x1BD11BDAu;
  x0 += k0; x1 += k1;
  tf_round4(x0, x1, 13, 15, 26, 6);  x0 += k1;  x1 += ks2 + 1u;
  tf_round4(x0, x1, 17, 29, 16, 24); x0 += ks2; x1 += k0  + 2u;
  tf_round4(x0, x1, 13, 15, 26, 6);  x0 += k0;  x1 += k1  + 3u;
  tf_round4(x0, x1, 17, 29, 16, 24); x0 += k1;  x1 += ks2 + 4u;
  tf_round4(x0, x1, 13, 15, 26, 6);  x0 += ks2; x1 += k0  + 5u;
  return make_uint2(x0, x1);
}

// uniform [0,1): bitcast((bits>>9)|0x3f800000) - 1  (exact, matches jax)
__device__ __forceinline__ float u01_from_bits(uint32_t bits) {
  return __fsub_rn(__uint_as_float((bits >> 9) | 0x3f800000u), 1.0f);
}

// ---------------------------------------------------------------------------
// XLA ErfInv (f32, Giles coefficients). Separate mul/add (XLA does not form
// FMAs), log1pf == libdevice __nv_log1pf (what XLA:GPU lowers Log1p to).
// ---------------------------------------------------------------------------
__device__ __forceinline__ float erfinv_xla(float x) {
  float w = -log1pf(-__fmul_rn(x, x));
  float p;
  if (w < 5.0f) {
    w = __fadd_rn(w, -2.5f);
    p = 2.81022636e-08f;
    p = __fadd_rn(3.43273939e-07f,  __fmul_rn(p, w));
    p = __fadd_rn(-3.5233877e-06f,  __fmul_rn(p, w));
    p = __fadd_rn(-4.39150654e-06f, __fmul_rn(p, w));
    p = __fadd_rn(0.00021858087f,   __fmul_rn(p, w));
    p = __fadd_rn(-0.00125372503f,  __fmul_rn(p, w));
    p = __fadd_rn(-0.00417768164f,  __fmul_rn(p, w));
    p = __fadd_rn(0.246640727f,     __fmul_rn(p, w));
    p = __fadd_rn(1.50140941f,      __fmul_rn(p, w));
  } else {
    w = __fadd_rn(__fsqrt_rn(w), -3.0f);
    p = -0.000200214257f;
    p = __fadd_rn(0.000100950558f,  __fmul_rn(p, w));
    p = __fadd_rn(0.00134934322f,   __fmul_rn(p, w));
    p = __fadd_rn(-0.00367342844f,  __fmul_rn(p, w));
    p = __fadd_rn(0.00573950773f,   __fmul_rn(p, w));
    p = __fadd_rn(-0.0076224613f,   __fmul_rn(p, w));
    p = __fadd_rn(0.00943887047f,   __fmul_rn(p, w));
    p = __fadd_rn(1.00167406f,      __fmul_rn(p, w));
    p = __fadd_rn(2.83297682f,      __fmul_rn(p, w));
  }
  return __fmul_rn(p, x);
}

// ---------------------------------------------------------------------------
// K0: per-step key derivation.
// split(key(0), T)[t] = TF((0,0), (0,t)) ; kn = TF(kt,(0,0)) ; kb = TF(kt,(0,1))
// ---------------------------------------------------------------------------
__global__ void __launch_bounds__(256) k_keys() {
  int t = blockIdx.x * blockDim.x + threadIdx.x;
  if (t >= T_STEPS) return;
  uint2 kt = threefry2x32(0u, 0u, 0u, (uint32_t)t);
  uint2 kn = threefry2x32(kt.x, kt.y, 0u, 0u);
  uint2 kb = threefry2x32(kt.x, kt.y, 0u, 1u);
  g_keys[t] = make_uint4(kn.x, kn.y, kb.x, kb.y);
}

// ---------------------------------------------------------------------------
// K1: noise generation, parallel over (i, t). Thread = (one neuron i, 32
// consecutive t) -> writes one full 128B line of neuron-major g_noise.
// normal bits (partitionable): TF(kn_t, (0, i)).x ^ .y
// ---------------------------------------------------------------------------
__global__ void __launch_bounds__(256) k_noise() {
  __shared__ uint2 skn[32];
  const int IB = N_NEUR / 256;               // 32 i-blocks
  int iblk = blockIdx.x % IB;
  int tblk = blockIdx.x / IB;
  int i  = iblk * 256 + threadIdx.x;
  int t0 = tblk * 32;

  if (threadIdx.x < 32) {
    uint4 k = g_keys[t0 + threadIdx.x];
    skn[threadIdx.x] = make_uint2(k.x, k.y);
  }
  __syncthreads();

  const float LO  = __uint_as_float(0xBF7FFFFFu);   // nextafter(-1, 0)
  const float SQ2 = __uint_as_float(0x3FB504F3u);   // float(sqrt(2))
  const float NS  = (float)(0.6 * sqrt(0.001));     // sigma * sqrt(dt)

  float* dst = g_noise + (size_t)i * T_STEPS + t0;

  for (int jj = 0; jj < 32; jj += 4) {
    float tmp[4];
#pragma unroll
    for (int j = 0; j < 4; j++) {
      uint2 kn = skn[jj + j];
      uint2 r  = threefry2x32(kn.x, kn.y, 0u, (uint32_t)i);
      float f  = u01_from_bits(r.x ^ r.y);
      float u  = __fadd_rn(__fmul_rn(f, 2.0f), LO);  // uniform in [lo, 1)
      u = fmaxf(LO, u);
      tmp[j] = __fmul_rn(__fmul_rn(SQ2, erfinv_xla(u)), NS);
    }
    float4 o; o.x = tmp[0]; o.y = tmp[1]; o.z = tmp[2]; o.w = tmp[3];
    *reinterpret_cast<float4*>(dst + jj) = o;
  }
}

// ---------------------------------------------------------------------------
// K2: serial OU scan per neuron (exact FP order), 8192 threads.
// Reads neuron-major noise (float4, double-buffered prefetch), writes x
// t-major into d_out (coalesced per step).
// ---------------------------------------------------------------------------
__global__ void __launch_bounds__(32) k_scan(const float* __restrict__ state,
                                             float* __restrict__ xout) {
  int i = blockIdx.x * 32 + threadIdx.x;
  float x = state[i];
  const float DT_F = 0.001f;
  const float4* src = reinterpret_cast<const float4*>(g_noise + (size_t)i * T_STEPS);

  float4 cur[8], nxt[8];
#pragma unroll
  for (int j = 0; j < 8; j++) cur[j] = __ldcs(&src[j]);

  for (int t0 = 0; t0 < T_STEPS; t0 += 32) {
    int pf = t0 + 32; if (pf > T_STEPS - 32) pf = T_STEPS - 32;
#pragma unroll
    for (int j = 0; j < 8; j++) nxt[j] = __ldcs(&src[pf / 4 + j]);

#pragma unroll
    for (int j = 0; j < 8; j++) {
      float n0 = cur[j].x, n1 = cur[j].y, n2 = cur[j].z, n3 = cur[j].w;
      x = __fadd_rn(__fsub_rn(x, __fmul_rn(x, DT_F)), n0);
      xout[(size_t)(t0 + j * 4 + 0) * N_NEUR + i] = x;
      x = __fadd_rn(__fsub_rn(x, __fmul_rn(x, DT_F)), n1);
      xout[(size_t)(t0 + j * 4 + 1) * N_NEUR + i] = x;
      x = __fadd_rn(__fsub_rn(x, __fmul_rn(x, DT_F)), n2);
      xout[(size_t)(t0 + j * 4 + 2) * N_NEUR + i] = x;
      x = __fadd_rn(__fsub_rn(x, __fmul_rn(x, DT_F)), n3);
      xout[(size_t)(t0 + j * 4 + 3) * N_NEUR + i] = x;
    }
#pragma unroll
    for (int j = 0; j < 8; j++) cur[j] = nxt[j];
  }
}

// ---------------------------------------------------------------------------
// K3: spikes, parallel over (t, 4 neurons). In-place on d_out:
// read x, compute uniform via TF(kb_t, (0, i)).x ^ .y, write spike.
// ---------------------------------------------------------------------------
__global__ void __launch_bounds__(256) k_spike(float* __restrict__ xo) {
  unsigned tid = blockIdx.x * 256u + threadIdx.x;
  unsigned t   = tid / (N_NEUR / 4);
  unsigned i0  = (tid % (N_NEUR / 4)) * 4u;
  uint4 kk = g_keys[t];
  size_t base = (size_t)t * N_NEUR + i0;

  float4 xv = *reinterpret_cast<const float4*>(xo + base);
  const float RDT = 0.003f;   // rate * dt (f32 of python 0.003)
  float xs[4] = {xv.x, xv.y, xv.z, xv.w};
  float sv[4];
#pragma unroll
  for (int j = 0; j < 4; j++) {
    uint2 r  = threefry2x32(kk.z, kk.w, 0u, i0 + (unsigned)j);
    float u  = u01_from_bits(r.x ^ r.y);
    float pr = __fadd_rn(RDT, xs[j]);
    pr = fminf(fmaxf(pr, 0.0f), 1.0f);   // jnp.clip: max then min
    sv[j] = (u < pr) ? 1.0f : 0.0f;
  }
  float4 s; s.x = sv[0]; s.y = sv[1]; s.z = sv[2]; s.w = sv[3];
  *reinterpret_cast<float4*>(xo + base) = s;
}

// ---------------------------------------------------------------------------
// launch
// ---------------------------------------------------------------------------
extern "C" void kernel_launch(void* const* d_in, const int* in_sizes, int n_in,
                              void* d_out, int out_size) {
  const float* state = (const float*)d_in[0];   // zeros [N]
  float* out = (float*)d_out;                   // f32 [T*N]

  k_keys <<<T_STEPS / 256, 256>>>();
  k_noise<<<(N_NEUR / 256) * (T_STEPS / 32), 256>>>();
  k_scan <<<N_NEUR / 32, 32>>>(state, out);
  k_spike<<<(unsigned)((size_t)T_STEPS * N_NEUR / 4 / 256), 256>>>(out);
}